// round 15
// baseline (speedup 1.0000x reference)
#include <cuda_runtime.h>
#include <cuda_fp16.h>
#include <cstdint>

// LeakageNlinCore as dense M=32768, N=128, K=128 GEMM via fp16 mma.m16n8k16.
// Round-15: shuffle-coalesced epilogue -> 4x STG.128 per warp-tile instead of
// 16x STG.64 (4x fewer store wavefronts; L1 was the hidden serializer).
// Rest is R14: upfront x+b burst, ldmatrix.x4 A loads, 512x256, 2 CTAs/SM.

#define NTHREADS 256
#define TILE_M   32
#define TILES    2
#define ROWS_CTA (TILE_M * TILES)   // 64
#define KDIM     128
#define NOUT     128
#define ST       68                 // F row stride in u32 (fp16x2 pairs + pad)

#define FB_U32 (TILE_M * ST)        // 2176 per buffer

// Fragment-ordered packed G (fp16x2): [cgrp(8)][j4(8)][lane(32)] uint4
// j = j4*4+e encodes (nb = j>>4, ks = (j>>1)&7, hb = j&1):
//   n = cgrp*16 + nb*8 + g,  k0 = 16*ks + 2*tg + 8*hb, pair (k0, k0+1)
__device__ uint4 Gpack16[8 * 8 * 32];

__device__ __forceinline__ uint32_t pack_h2(float lo, float hi) {
    __half2 h = __float22half2_rn(make_float2(lo, hi));
    return *(uint32_t*)&h;
}

__device__ __forceinline__ void mma_16x8x16(float& d0, float& d1, float& d2, float& d3,
                                            uint32_t a0, uint32_t a1, uint32_t a2, uint32_t a3,
                                            uint32_t b0, uint32_t b1) {
    asm volatile(
        "mma.sync.aligned.m16n8k16.row.col.f32.f16.f16.f32 "
        "{%0,%1,%2,%3}, {%4,%5,%6,%7}, {%8,%9}, {%0,%1,%2,%3};"
        : "+f"(d0), "+f"(d1), "+f"(d2), "+f"(d3)
        : "r"(a0), "r"(a1), "r"(a2), "r"(a3), "r"(b0), "r"(b1));
}

__device__ __forceinline__ void ldsm_x4(uint32_t& r0, uint32_t& r1,
                                        uint32_t& r2, uint32_t& r3, uint32_t addr) {
    asm volatile("ldmatrix.sync.aligned.m8n8.x4.shared.b16 {%0,%1,%2,%3}, [%4];"
                 : "=r"(r0), "=r"(r1), "=r"(r2), "=r"(r3) : "r"(addr));
}

// ---- Pre-kernel: LOO-expand W into fragment-ordered fp16x2 Gpack16 -------
__global__ void g_pack_kernel(const float* __restrict__ W) {
    int idx = blockIdx.x * blockDim.x + threadIdx.x;   // 0..2047
    int cgrp = idx >> 8;
    int j4 = (idx >> 5) & 7;
    int lane = idx & 31;
    int g = lane >> 2, tg = lane & 3;
    uint32_t pv[4];
#pragma unroll
    for (int e = 0; e < 4; e++) {
        int j = j4 * 4 + e;
        int nb = j >> 4, ks = (j >> 1) & 7, hb = j & 1;
        int n = cgrp * 16 + nb * 8 + g;
        int c = n >> 1;
        int k0 = 16 * ks + 2 * tg + 8 * hb;
        float v[2];
#pragma unroll
        for (int u = 0; u < 2; u++) {
            int k = k0 + u;
            int jj = k & 63, half = k >> 6;
            float gg = 0.0f;
            if (jj != c) gg = W[n * 126 + half * 63 + jj - (jj > c)];
            v[u] = gg;
        }
        pv[e] = pack_h2(v[0], v[1]);
    }
    Gpack16[idx] = make_uint4(pv[0], pv[1], pv[2], pv[3]);
}

// ---- Main kernel ----------------------------------------------------------
__global__ void __launch_bounds__(NTHREADS, 2)
leakage_main_kernel(const float* __restrict__ x, float* __restrict__ out) {
    __shared__ uint32_t Fb[2 * FB_U32];   // [2][32][ST] fp16x2 pairs

    const int tid = threadIdx.x;
    const int wid = tid >> 5;            // 0..7
    const int lid = tid & 31;
    const int g = lid >> 2;
    const int tg = lid & 3;
    const int cgrp = wid;                // 16-col group
    const size_t t0 = (size_t)blockIdx.x * ROWS_CTA;

    // ---- ONE upfront global burst: both tiles' x (8 float4) + B slice ----
    float4 r[8];
    {
        const float4* xb = (const float4*)(x + t0 * KDIM);
#pragma unroll
        for (int it = 0; it < 8; it++)
            r[it] = xb[(it * 8 + wid) * 32 + lid];   // rows 0..63
    }

    uint32_t b[2][8][2];
    {
        const uint4* gp = Gpack16 + cgrp * 256 + lid;
#pragma unroll
        for (int j4 = 0; j4 < 8; j4++) {
            uint4 q = gp[j4 * 32];
#pragma unroll
            for (int e = 0; e < 4; e++) {
                const int j = j4 * 4 + e;
                const int nb = j >> 4, ks = (j >> 1) & 7, hb = j & 1;
                uint32_t val = (e == 0) ? q.x : (e == 1) ? q.y : (e == 2) ? q.z : q.w;
                b[nb][ks][hb] = val;
            }
        }
    }

    // ldmatrix lane addressing (within a 32-row tile buffer):
    const uint32_t lrow = (lid & 7) + 8 * ((lid >> 3) & 1);
    const uint32_t lkoff = ((lid >> 4) & 1) * 4;
    const uint32_t smem_base = (uint32_t)__cvta_generic_to_shared(Fb);

#pragma unroll
    for (int t = 0; t < TILES; t++) {
        uint32_t* buf = Fb + (t & 1) * FB_U32;

        // ---- Transform r -> F (fp16x2), conflict-free STS.32 ----
#pragma unroll
        for (int it = 0; it < 4; it++) {
            float4 v = r[t * 4 + it];
            float amp0 = v.x * v.x + v.y * v.y;
            float amp1 = v.z * v.z + v.w * v.w;
            uint32_t frp = pack_h2(amp0 * v.x, amp1 * v.z);
            uint32_t fip = pack_h2(amp0 * v.y, amp1 * v.w);
            uint32_t* rowp = buf + (it * 8 + wid) * ST;
            rowp[lid] = frp;        // k pair (2lid, 2lid+1)     -> fr
            rowp[32 + lid] = fip;   // k pair (64+2lid, 65+2lid) -> fi
        }
        __syncthreads();

        // ---- Mainloop: 32 rows x 16 cols, 8 k-chunks of 16, ldmatrix A ----
        float acc[2][2][4];
#pragma unroll
        for (int mt = 0; mt < 2; mt++)
#pragma unroll
            for (int nb = 0; nb < 2; nb++)
#pragma unroll
                for (int q = 0; q < 4; q++) acc[mt][nb][q] = 0.0f;

        const uint32_t abase0 = smem_base +
            ((t & 1) * FB_U32 + lrow * ST + lkoff) * 4;
        const uint32_t abase1 = abase0 + 16 * ST * 4;

#pragma unroll
        for (int ks = 0; ks < 8; ks++) {
            uint32_t a0, a1, a2, a3, c0, c1, c2, c3;
            ldsm_x4(a0, a1, a2, a3, abase0 + ks * 32);
            ldsm_x4(c0, c1, c2, c3, abase1 + ks * 32);
            mma_16x8x16(acc[0][0][0], acc[0][0][1], acc[0][0][2], acc[0][0][3],
                        a0, a1, a2, a3, b[0][ks][0], b[0][ks][1]);
            mma_16x8x16(acc[0][1][0], acc[0][1][1], acc[0][1][2], acc[0][1][3],
                        a0, a1, a2, a3, b[1][ks][0], b[1][ks][1]);
            mma_16x8x16(acc[1][0][0], acc[1][0][1], acc[1][0][2], acc[1][0][3],
                        c0, c1, c2, c3, b[0][ks][0], b[0][ks][1]);
            mma_16x8x16(acc[1][1][0], acc[1][1][1], acc[1][1][2], acc[1][1][3],
                        c0, c1, c2, c3, b[1][ks][0], b[1][ks][1]);
        }

        // ---- Epilogue: shuffle-coalesce -> STG.128 ----
        // Lane tg gathers cols [4tg, 4tg+4) of its row from lanes 2(tg&1),
        // 2(tg&1)+1 (nb0 pair if tg<2, nb1 pair if tg>=2).
        const size_t rbase = t0 + (size_t)t * TILE_M;
        const int src0 = (lid & ~3) | ((tg & 1) * 2);
        const int src1 = src0 + 1;
#pragma unroll
        for (int mt = 0; mt < 2; mt++) {
#pragma unroll
            for (int h = 0; h < 2; h++) {
                float p0x = acc[mt][0][2 * h], p0y = acc[mt][0][2 * h + 1];
                float p1x = acc[mt][1][2 * h], p1y = acc[mt][1][2 * h + 1];
                float t00 = __shfl_sync(0xffffffffu, p0x, src0);
                float t01 = __shfl_sync(0xffffffffu, p0y, src0);
                float t02 = __shfl_sync(0xffffffffu, p0x, src1);
                float t03 = __shfl_sync(0xffffffffu, p0y, src1);
                float t10 = __shfl_sync(0xffffffffu, p1x, src0);
                float t11 = __shfl_sync(0xffffffffu, p1y, src0);
                float t12 = __shfl_sync(0xffffffffu, p1x, src1);
                float t13 = __shfl_sync(0xffffffffu, p1y, src1);
                float4 q = (tg < 2) ? make_float4(t00, t01, t02, t03)
                                    : make_float4(t10, t11, t12, t13);
                const size_t row = rbase + mt * 16 + 8 * h + g;
                *(float4*)(out + row * NOUT + cgrp * 16 + tg * 4) = q;
            }
        }
        // No trailing sync: TILES=2 uses distinct buffers, never reused.
    }
}

extern "C" void kernel_launch(void* const* d_in, const int* in_sizes, int n_in,
                              void* d_out, int out_size) {
    const float* x = (const float*)d_in[0];  // [B,S,C,2] fp32
    const float* W = (const float*)d_in[1];  // [C,2,126] fp32
    float* out = (float*)d_out;              // [B,S,C,2] fp32

    int tokens = in_sizes[0] / KDIM;         // 32768
    int nblocks = tokens / ROWS_CTA;         // 512

    g_pack_kernel<<<32, 64>>>(W);
    leakage_main_kernel<<<nblocks, NTHREADS>>>(x, out);
}